// round 4
// baseline (speedup 1.0000x reference)
#include <cuda_runtime.h>
#include <math_constants.h>
#include <cstdint>

// Problem shape (fixed)
#define Bdim 2048
#define Ddim 25088
#define Cdim 100
#define CPAD 128

#define SPLITS 8
#define KC (Ddim / SPLITS)      // 3136
#define KT 32                   // bf16 K per iteration
#define ITERS (KC / KT)         // 98
#define BM 128

// smem tile geometry: 128 rows x 32 bf16, row stride padded to 80 B
#define STR 80
#define TILE_SZ (128 * STR)              // 10240 B
#define BUF_SZ (4 * TILE_SZ)             // Ahi, Alo, Bhi, Blo
#define SMEM_TOTAL (2 * BUF_SZ)          // 81920 B

#define W32 12544                        // u32 per W row (25088 bf16)

// ---------------- scratch ----------------
__device__ float    g_part[(size_t)SPLITS * Bdim * CPAD];  // 8 MB split partials
__device__ float    g_nfsq[SPLITS * 4 * Bdim];             // feature norm^2 partials
__device__ uint32_t g_whi[(size_t)CPAD * W32];             // normalized W, bf16 hi
__device__ uint32_t g_wlo[(size_t)CPAD * W32];             // normalized W, bf16 lo
__device__ float    g_nll[Bdim];
__device__ float    g_corr[Bdim];
__device__ float    g_vld[Bdim];
__device__ int      g_is64;

// ---------------- helpers ----------------
__device__ __forceinline__ uint32_t smem_u32(const void* p) {
    uint32_t a;
    asm("{ .reg .u64 t; cvta.to.shared.u64 t, %1; cvt.u32.u64 %0, t; }" : "=r"(a) : "l"(p));
    return a;
}
__device__ __forceinline__ void ldsm4(uint32_t addr, uint32_t& r0, uint32_t& r1,
                                      uint32_t& r2, uint32_t& r3) {
    asm volatile("ldmatrix.sync.aligned.m8n8.x4.shared.b16 {%0,%1,%2,%3}, [%4];"
                 : "=r"(r0), "=r"(r1), "=r"(r2), "=r"(r3) : "r"(addr));
}
__device__ __forceinline__ void mma_bf16(float& d0, float& d1, float& d2, float& d3,
                                         uint32_t a0, uint32_t a1, uint32_t a2, uint32_t a3,
                                         uint32_t b0, uint32_t b1) {
    asm volatile("mma.sync.aligned.m16n8k16.row.col.f32.bf16.bf16.f32 "
                 "{%0,%1,%2,%3}, {%4,%5,%6,%7}, {%8,%9}, {%0,%1,%2,%3};"
                 : "+f"(d0), "+f"(d1), "+f"(d2), "+f"(d3)
                 : "r"(a0), "r"(a1), "r"(a2), "r"(a3), "r"(b0), "r"(b1));
}
// pack 2 floats -> bf16x2 hi, residuals -> bf16x2 lo
__device__ __forceinline__ void cvt2(float x, float y, uint32_t& hi, uint32_t& lo) {
    asm("cvt.rn.bf16x2.f32 %0, %1, %2;" : "=r"(hi) : "f"(y), "f"(x));
    float fx = __uint_as_float(hi << 16);
    float fy = __uint_as_float(hi & 0xFFFF0000u);
    asm("cvt.rn.bf16x2.f32 %0, %1, %2;" : "=r"(lo) : "f"(y - fy), "f"(x - fx));
}
#define CP16(dst, src) asm volatile("cp.async.cg.shared.global [%0], [%1], 16;" :: "r"(dst), "l"(src))
#define CP_COMMIT()    asm volatile("cp.async.commit_group;" ::: "memory")
#define CP_WAIT1()     asm volatile("cp.async.wait_group 1;" ::: "memory")
#define CP_WAIT0()     asm volatile("cp.async.wait_group 0;" ::: "memory")

// ======================= label dtype sniffing (parallel) =======================
__global__ void detect_label_kernel(const int* __restrict__ l32, int nlab) {
    __shared__ int s_ok[2];
    const int t = threadIdx.x;                 // 64 threads
    const int n = nlab < 64 ? nlab : 64;
    int ok = 1;
    if (t < n) {
        int hi = l32[2 * t + 1];
        ok = (hi == 0 || hi == -1) ? 1 : 0;
    }
    unsigned b = __ballot_sync(0xFFFFFFFFu, ok);
    if ((t & 31) == 0) s_ok[t >> 5] = (b == 0xFFFFFFFFu);
    __syncthreads();
    if (t == 0) g_is64 = (s_ok[0] && s_ok[1]) ? 1 : 0;
}

// ======================= W prep: norm + normalize + bf16 hi/lo =================
__global__ __launch_bounds__(256) void prep_w_kernel(const float* __restrict__ W) {
    const int row = blockIdx.x;                // 0..127
    const int t   = threadIdx.x;
    __shared__ float red[256];
    __shared__ float s_inv;

    if (row < Cdim) {
        const float4* r4 = (const float4*)(W + (size_t)row * Ddim);
        float s = 0.f;
        for (int i = t; i < Ddim / 4; i += 256) {
            float4 v = r4[i];
            s += v.x * v.x + v.y * v.y + v.z * v.z + v.w * v.w;
        }
        red[t] = s;
        __syncthreads();
        for (int off = 128; off > 0; off >>= 1) {
            if (t < off) red[t] += red[t + off];
            __syncthreads();
        }
        if (t == 0) s_inv = 1.0f / fmaxf(sqrtf(red[0]), 1e-8f);
        __syncthreads();
        const float inv = s_inv;
        const float2* r2 = (const float2*)(W + (size_t)row * Ddim);
        uint32_t* dh = &g_whi[(size_t)row * W32];
        uint32_t* dl = &g_wlo[(size_t)row * W32];
        for (int i = t; i < W32; i += 256) {
            float2 v = r2[i];
            uint32_t hi, lo;
            cvt2(v.x * inv, v.y * inv, hi, lo);
            dh[i] = hi;
            dl[i] = lo;
        }
    } else {
        uint32_t* dh = &g_whi[(size_t)row * W32];
        uint32_t* dl = &g_wlo[(size_t)row * W32];
        for (int i = t; i < W32; i += 256) { dh[i] = 0u; dl[i] = 0u; }
    }
}

// ======================= HMMA split-bf16 GEMM =======================
// grid (Bdim/BM, SPLITS), 512 threads. Warp grid 4(M) x 4(N), warp tile 32x32.
// A: LDG fp32 -> reg cvt -> STS (hi/lo). B: cp.async of pre-converted bf16.
__global__ void __launch_bounds__(512, 1)
gemm_mma_kernel(const float* __restrict__ F) {
    extern __shared__ char smem[];
    const uint32_t sbase = smem_u32(smem);

    const int t     = threadIdx.x;
    const int lane  = t & 31;
    const int w     = t >> 5;
    const int m0    = blockIdx.x * BM;
    const int split = blockIdx.y;
    const int k0    = split * KC;

    // ---- loader mapping: row = t/4 (0..127), quarter q = t&3 (8 floats) ----
    const int row = t >> 2;
    const int q   = t & 3;

    const float4* gA = (const float4*)(F + (size_t)(m0 + row) * Ddim + k0) + 2 * q;
    const uint32_t stsA_off = row * STR + q * 16;   // within Ahi tile
    // B sources (bf16, pre-normalized): row stride 50176 B, per-iter step 64 B
    const char* srcBh = (const char*)g_whi + (size_t)row * (W32 * 4) + (size_t)k0 * 2 + q * 16;
    const char* srcBl = (const char*)g_wlo + (size_t)row * (W32 * 4) + (size_t)k0 * 2 + q * 16;
    const uint32_t dstB_off = 2 * TILE_SZ + row * STR + q * 16;

    // ---- MMA mapping ----
    const int wm = w >> 2;
    const int wn = w & 3;
    const uint32_t aAddr0 = sbase + (wm * 32 + (lane & 15)) * STR + (lane >> 4) * 16;
    const uint32_t bAddr0 = sbase + 2 * TILE_SZ +
        (wn * 32 + (lane & 7) + (lane >> 4) * 8) * STR + ((lane >> 3) & 1) * 16;

    float acc[2][4][4];
#pragma unroll
    for (int i = 0; i < 2; i++)
#pragma unroll
        for (int j = 0; j < 4; j++)
#pragma unroll
            for (int e = 0; e < 4; e++) acc[i][j][e] = 0.f;

    float nf = 0.f;
    float4 ra0, ra1;

    // prologue: A tile 0 regs, B tile 0 cp.async into buf0
    ra0 = gA[0]; ra1 = gA[1];
    CP16(sbase + dstB_off, srcBh);
    CP16(sbase + dstB_off + TILE_SZ, srcBl);
    CP_COMMIT();

    for (int it = 0; it < ITERS; it++) {
        const uint32_t bufo = (it & 1) ? BUF_SZ : 0;
        const uint32_t nbuf = (it & 1) ? 0 : BUF_SZ;

        __syncthreads();   // buf writable (prior MMA reads done)

        // issue B(it+1) into other buffer
        if (it + 1 < ITERS) {
            CP16(sbase + nbuf + dstB_off, srcBh + (size_t)(it + 1) * 64);
            CP16(sbase + nbuf + dstB_off + TILE_SZ, srcBl + (size_t)(it + 1) * 64);
            CP_COMMIT();
        }

        // convert + store A tile it
        nf += ra0.x * ra0.x + ra0.y * ra0.y + ra0.z * ra0.z + ra0.w * ra0.w
            + ra1.x * ra1.x + ra1.y * ra1.y + ra1.z * ra1.z + ra1.w * ra1.w;
        {
            uint32_t h0, h1, h2, h3, l0, l1, l2, l3;
            cvt2(ra0.x, ra0.y, h0, l0); cvt2(ra0.z, ra0.w, h1, l1);
            cvt2(ra1.x, ra1.y, h2, l2); cvt2(ra1.z, ra1.w, h3, l3);
            *(uint4*)(smem + bufo + stsA_off)           = make_uint4(h0, h1, h2, h3);
            *(uint4*)(smem + bufo + stsA_off + TILE_SZ) = make_uint4(l0, l1, l2, l3);
        }

        // prefetch A(it+1) (covered by the MMA phase)
        if (it + 1 < ITERS) {
            ra0 = gA[(it + 1) * 8];
            ra1 = gA[(it + 1) * 8 + 1];
        }

        if (it + 1 < ITERS) { CP_WAIT1(); } else { CP_WAIT0(); }
        __syncthreads();   // tile it fully visible

        // MMA: 2 k16 steps x (2 m-frags x 2 n16-groups) x 3 terms
#pragma unroll
        for (int ks = 0; ks < 2; ks++) {
            uint32_t ah[2][4], al[2][4], bh[2][4], bl[2][4];
#pragma unroll
            for (int mi = 0; mi < 2; mi++) {
                const uint32_t a = aAddr0 + bufo + mi * 16 * STR + ks * 32;
                ldsm4(a,           ah[mi][0], ah[mi][1], ah[mi][2], ah[mi][3]);
                ldsm4(a + TILE_SZ, al[mi][0], al[mi][1], al[mi][2], al[mi][3]);
            }
#pragma unroll
            for (int ni = 0; ni < 2; ni++) {
                const uint32_t b = bAddr0 + bufo + ni * 16 * STR + ks * 32;
                ldsm4(b,           bh[ni][0], bh[ni][1], bh[ni][2], bh[ni][3]);
                ldsm4(b + TILE_SZ, bl[ni][0], bl[ni][1], bl[ni][2], bl[ni][3]);
            }
#pragma unroll
            for (int mi = 0; mi < 2; mi++)
#pragma unroll
                for (int ni = 0; ni < 2; ni++)
#pragma unroll
                    for (int h = 0; h < 2; h++) {
                        float* d = acc[mi][ni * 2 + h];
                        const uint32_t b0 = bh[ni][2 * h], b1 = bh[ni][2 * h + 1];
                        const uint32_t c0 = bl[ni][2 * h], c1 = bl[ni][2 * h + 1];
                        mma_bf16(d[0], d[1], d[2], d[3],
                                 ah[mi][0], ah[mi][1], ah[mi][2], ah[mi][3], b0, b1);
                        mma_bf16(d[0], d[1], d[2], d[3],
                                 ah[mi][0], ah[mi][1], ah[mi][2], ah[mi][3], c0, c1);
                        mma_bf16(d[0], d[1], d[2], d[3],
                                 al[mi][0], al[mi][1], al[mi][2], al[mi][3], b0, b1);
                    }
        }
    }

    // feature norm^2 partial
    g_nfsq[(split * 4 + q) * Bdim + (m0 + row)] = nf;

    // write partials
#pragma unroll
    for (int mi = 0; mi < 2; mi++)
#pragma unroll
        for (int nj = 0; nj < 4; nj++)
#pragma unroll
            for (int e = 0; e < 4; e++) {
                const int r = m0 + wm * 32 + mi * 16 + (lane >> 2) + (e >> 1) * 8;
                const int c = wn * 32 + nj * 8 + (lane & 3) * 2 + (e & 1);
                g_part[((size_t)split * Bdim + r) * CPAD + c] = acc[mi][nj][e];
            }
}

// ======================= per-row epilogue =======================
__global__ __launch_bounds__(128) void epilogue_kernel(const void* __restrict__ labels) {
    const int row = blockIdx.x;
    const int t   = threadIdx.x;

    __shared__ float sv[128];
    __shared__ int   si[128];
    __shared__ float slog[128];
    __shared__ float s_nf;

    // parallel feature-norm reduction (warp 0, 32 partials)
    if (t < 32) {
        float s = g_nfsq[t * Bdim + row];
#pragma unroll
        for (int off = 16; off > 0; off >>= 1)
            s += __shfl_down_sync(0xFFFFFFFFu, s, off);
        if (t == 0) s_nf = fmaxf(sqrtf(s), 1e-8f);
    }

    float g = 0.f;
#pragma unroll
    for (int s = 0; s < SPLITS; s++)
        g += g_part[((size_t)s * Bdim + row) * CPAD + t];
    __syncthreads();

    const float logit = (t < Cdim) ? 10.0f * g / s_nf : -CUDART_INF_F;
    slog[t] = logit;
    sv[t]   = logit;
    si[t]   = t;
    __syncthreads();

    for (int off = 64; off > 0; off >>= 1) {
        if (t < off) {
            float v2 = sv[t + off]; int i2 = si[t + off];
            if (v2 > sv[t] || (v2 == sv[t] && i2 < si[t])) { sv[t] = v2; si[t] = i2; }
        }
        __syncthreads();
    }
    const float mx   = sv[0];
    const int   amax = si[0];
    __syncthreads();

    sv[t] = (t < Cdim) ? expf(logit - mx) : 0.f;
    __syncthreads();
    for (int off = 64; off > 0; off >>= 1) {
        if (t < off) sv[t] += sv[t + off];
        __syncthreads();
    }

    if (t == 0) {
        const float lse = logf(sv[0]) + mx;
        long long lab;
        if (g_is64) lab = ((const long long*)labels)[row];
        else        lab = (long long)((const int*)labels)[row];
        const bool valid = (lab >= 0);
        float nll = 0.f, corr = 0.f;
        if (valid) {
            nll  = lse - slog[(int)lab];
            corr = (amax == (int)lab) ? 1.f : 0.f;
        }
        g_nll[row]  = nll;
        g_corr[row] = corr;
        g_vld[row]  = valid ? 1.f : 0.f;
    }
}

// ======================= finalize =======================
__global__ __launch_bounds__(256) void finalize_kernel(float* __restrict__ out,
                                                       int out_size) {
    __shared__ float sn[256], sc[256], sd[256];
    const int t = threadIdx.x;
    float a = 0.f, b = 0.f, c = 0.f;
    for (int i = t; i < Bdim; i += 256) {
        a += g_nll[i]; b += g_corr[i]; c += g_vld[i];
    }
    sn[t] = a; sc[t] = b; sd[t] = c;
    __syncthreads();
    for (int off = 128; off > 0; off >>= 1) {
        if (t < off) { sn[t] += sn[t + off]; sc[t] += sc[t + off]; sd[t] += sd[t + off]; }
        __syncthreads();
    }
    if (t == 0) {
        const float nv = sd[0];
        out[0] = sn[0] / fmaxf(nv, 1.0f);
        if (out_size > 1) out[1] = sc[0] / (nv + 1e-10f);
    }
}

// ======================= launch =======================
extern "C" void kernel_launch(void* const* d_in, const int* in_sizes, int n_in,
                              void* d_out, int out_size) {
    int fi = 0, li = 0;
    for (int i = 1; i < n_in; i++) {
        if (in_sizes[i] > in_sizes[fi]) fi = i;
        if (in_sizes[i] < in_sizes[li]) li = i;
    }
    int wi = 0;
    for (int i = 0; i < n_in; i++) if (i != fi && i != li) wi = i;

    const float* F = (const float*)d_in[fi];
    const float* W = (const float*)d_in[wi];
    const void*  L = d_in[li];
    const int nlab = in_sizes[li];

    cudaFuncSetAttribute(gemm_mma_kernel,
                         cudaFuncAttributeMaxDynamicSharedMemorySize, SMEM_TOTAL);

    detect_label_kernel<<<1, 64>>>((const int*)L, nlab);
    prep_w_kernel<<<CPAD, 256>>>(W);
    gemm_mma_kernel<<<dim3(Bdim / BM, SPLITS), 512, SMEM_TOTAL>>>(F);
    epilogue_kernel<<<Bdim, 128>>>(L);
    finalize_kernel<<<1, 256>>>((float*)d_out, out_size);
}

// round 5
// speedup vs baseline: 1.6332x; 1.6332x over previous
#include <cuda_runtime.h>
#include <math_constants.h>
#include <cstdint>

// Problem shape (fixed)
#define Bdim 2048
#define Ddim 25088
#define Cdim 100
#define CPAD 128

#define SPLITS 8
#define KC (Ddim / SPLITS)      // 3136
#define KT 32                   // fp16 K per iteration
#define ITERS (KC / KT)         // 98
#define BM 128

// smem tile geometry: 128 rows x 32 fp16 (64 B), row stride padded to 80 B
#define STR 80
#define TILE_SZ (128 * STR)              // 10240 B
#define BUF_SZ (2 * TILE_SZ)             // A, B
#define SMEM_TOTAL (2 * BUF_SZ)          // 40960 B

#define W32 12544                        // u32 per W row (25088 fp16)

// ---------------- scratch ----------------
__device__ float    g_part[(size_t)SPLITS * Bdim * CPAD];  // 8 MB split partials
__device__ float    g_nfsq[SPLITS * 4 * Bdim];             // feature norm^2 partials
__device__ uint32_t g_wh[(size_t)CPAD * W32];              // normalized W, fp16
__device__ float    g_nll[Bdim];
__device__ float    g_corr[Bdim];
__device__ float    g_vld[Bdim];

// ---------------- helpers ----------------
__device__ __forceinline__ uint32_t smem_u32(const void* p) {
    uint32_t a;
    asm("{ .reg .u64 t; cvta.to.shared.u64 t, %1; cvt.u32.u64 %0, t; }" : "=r"(a) : "l"(p));
    return a;
}
__device__ __forceinline__ void ldsm4(uint32_t addr, uint32_t& r0, uint32_t& r1,
                                      uint32_t& r2, uint32_t& r3) {
    asm volatile("ldmatrix.sync.aligned.m8n8.x4.shared.b16 {%0,%1,%2,%3}, [%4];"
                 : "=r"(r0), "=r"(r1), "=r"(r2), "=r"(r3) : "r"(addr));
}
__device__ __forceinline__ void mma_f16(float& d0, float& d1, float& d2, float& d3,
                                        uint32_t a0, uint32_t a1, uint32_t a2, uint32_t a3,
                                        uint32_t b0, uint32_t b1) {
    asm volatile("mma.sync.aligned.m16n8k16.row.col.f32.f16.f16.f32 "
                 "{%0,%1,%2,%3}, {%4,%5,%6,%7}, {%8,%9}, {%0,%1,%2,%3};"
                 : "+f"(d0), "+f"(d1), "+f"(d2), "+f"(d3)
                 : "r"(a0), "r"(a1), "r"(a2), "r"(a3), "r"(b0), "r"(b1));
}
// pack 2 floats -> f16x2 (lo = x, hi = y)
__device__ __forceinline__ uint32_t cvt_f16x2(float x, float y) {
    uint32_t r;
    asm("cvt.rn.f16x2.f32 %0, %1, %2;" : "=r"(r) : "f"(y), "f"(x));
    return r;
}
#define CP16(dst, src) asm volatile("cp.async.cg.shared.global [%0], [%1], 16;" :: "r"(dst), "l"(src))
#define CP_COMMIT()    asm volatile("cp.async.commit_group;" ::: "memory")
#define CP_WAIT1()     asm volatile("cp.async.wait_group 1;" ::: "memory")
#define CP_WAIT0()     asm volatile("cp.async.wait_group 0;" ::: "memory")

// ======================= W prep: norm + normalize + fp16 =======================
__global__ __launch_bounds__(256) void prep_w_kernel(const float* __restrict__ W) {
    const int row = blockIdx.x;                // 0..127
    const int t   = threadIdx.x;
    __shared__ float red[256];
    __shared__ float s_inv;

    uint32_t* dh = &g_wh[(size_t)row * W32];
    if (row < Cdim) {
        const float4* r4 = (const float4*)(W + (size_t)row * Ddim);
        float s = 0.f;
        for (int i = t; i < Ddim / 4; i += 256) {
            float4 v = r4[i];
            s += v.x * v.x + v.y * v.y + v.z * v.z + v.w * v.w;
        }
        red[t] = s;
        __syncthreads();
        for (int off = 128; off > 0; off >>= 1) {
            if (t < off) red[t] += red[t + off];
            __syncthreads();
        }
        if (t == 0) s_inv = 1.0f / fmaxf(sqrtf(red[0]), 1e-8f);
        __syncthreads();
        const float inv = s_inv;
        const float2* r2 = (const float2*)(W + (size_t)row * Ddim);
        for (int i = t; i < W32; i += 256) {
            float2 v = r2[i];
            dh[i] = cvt_f16x2(v.x * inv, v.y * inv);
        }
    } else {
        for (int i = t; i < W32; i += 256) dh[i] = 0u;
    }
}

// ======================= HMMA fp16 GEMM =======================
// grid (Bdim/BM, SPLITS), 512 threads. Warp grid 4(M) x 4(N), warp tile 32x32.
// A: LDG fp32 (2-stage reg prefetch) -> cvt fp16 -> STS. B: cp.async of prepped fp16.
__global__ void __launch_bounds__(512, 1)
gemm_mma_kernel(const float* __restrict__ F) {
    extern __shared__ char smem[];
    const uint32_t sbase = smem_u32(smem);

    const int t     = threadIdx.x;
    const int lane  = t & 31;
    const int w     = t >> 5;
    const int m0    = blockIdx.x * BM;
    const int split = blockIdx.y;
    const int k0    = split * KC;

    // ---- loader mapping: row = t/4 (0..127), quarter q = t&3 (8 floats) ----
    const int row = t >> 2;
    const int q   = t & 3;

    const float4* gA = (const float4*)(F + (size_t)(m0 + row) * Ddim + k0) + 2 * q;
    const uint32_t stsA_off = row * STR + q * 16;   // within A tile
    const char* srcB = (const char*)g_wh + (size_t)row * (W32 * 4) + (size_t)k0 * 2 + q * 16;
    const uint32_t dstB_off = TILE_SZ + row * STR + q * 16;

    // ---- MMA mapping ----
    const int wm = w >> 2;
    const int wn = w & 3;
    const uint32_t aAddr0 = sbase + (wm * 32 + (lane & 15)) * STR + (lane >> 4) * 16;
    const uint32_t bAddr0 = sbase + TILE_SZ +
        (wn * 32 + (lane & 7) + (lane >> 4) * 8) * STR + ((lane >> 3) & 1) * 16;

    float acc[2][4][4];
#pragma unroll
    for (int i = 0; i < 2; i++)
#pragma unroll
        for (int j = 0; j < 4; j++)
#pragma unroll
            for (int e = 0; e < 4; e++) acc[i][j][e] = 0.f;

    float nf = 0.f;
    float4 ra[2][2];    // 2-stage A prefetch (tiles it, it+1)

    // prologue: A tiles 0,1 into regs; B tile 0 cp.async into buf0
    ra[0][0] = gA[0];  ra[0][1] = gA[1];
    ra[1][0] = gA[8];  ra[1][1] = gA[9];
    CP16(sbase + dstB_off, srcB);
    CP_COMMIT();

    for (int it = 0; it < ITERS; it++) {
        const uint32_t bufo = (it & 1) ? BUF_SZ : 0;
        const uint32_t nbuf = (it & 1) ? 0 : BUF_SZ;
        const int slot = it & 1;

        __syncthreads();   // buf writable (prior MMA reads done)

        // issue B(it+1) into other buffer
        if (it + 1 < ITERS) {
            CP16(sbase + nbuf + dstB_off, srcB + (size_t)(it + 1) * 64);
            CP_COMMIT();
        }

        // convert + store A tile `it`
        {
            float4 v0 = ra[slot][0], v1 = ra[slot][1];
            nf += v0.x * v0.x + v0.y * v0.y + v0.z * v0.z + v0.w * v0.w
                + v1.x * v1.x + v1.y * v1.y + v1.z * v1.z + v1.w * v1.w;
            uint4 pk;
            pk.x = cvt_f16x2(v0.x, v0.y);
            pk.y = cvt_f16x2(v0.z, v0.w);
            pk.z = cvt_f16x2(v1.x, v1.y);
            pk.w = cvt_f16x2(v1.z, v1.w);
            *(uint4*)(smem + bufo + stsA_off) = pk;
        }

        // prefetch A(it+2) into freed slot
        if (it + 2 < ITERS) {
            ra[slot][0] = gA[(it + 2) * 8];
            ra[slot][1] = gA[(it + 2) * 8 + 1];
        }

        if (it + 1 < ITERS) { CP_WAIT1(); } else { CP_WAIT0(); }
        __syncthreads();   // tile `it` fully visible

        // MMA: 2 k16 steps x (2 m-frags x 2 n16-groups x 2 n8-halves)
#pragma unroll
        for (int ks = 0; ks < 2; ks++) {
            uint32_t ah[2][4], bh[2][4];
#pragma unroll
            for (int mi = 0; mi < 2; mi++) {
                const uint32_t a = aAddr0 + bufo + mi * 16 * STR + ks * 32;
                ldsm4(a, ah[mi][0], ah[mi][1], ah[mi][2], ah[mi][3]);
            }
#pragma unroll
            for (int ni = 0; ni < 2; ni++) {
                const uint32_t b = bAddr0 + bufo + ni * 16 * STR + ks * 32;
                ldsm4(b, bh[ni][0], bh[ni][1], bh[ni][2], bh[ni][3]);
            }
#pragma unroll
            for (int mi = 0; mi < 2; mi++)
#pragma unroll
                for (int ni = 0; ni < 2; ni++)
#pragma unroll
                    for (int h = 0; h < 2; h++) {
                        float* d = acc[mi][ni * 2 + h];
                        mma_f16(d[0], d[1], d[2], d[3],
                                ah[mi][0], ah[mi][1], ah[mi][2], ah[mi][3],
                                bh[ni][2 * h], bh[ni][2 * h + 1]);
                    }
        }
    }

    // feature norm^2 partial
    g_nfsq[(split * 4 + q) * Bdim + (m0 + row)] = nf;

    // write partials
#pragma unroll
    for (int mi = 0; mi < 2; mi++)
#pragma unroll
        for (int nj = 0; nj < 4; nj++)
#pragma unroll
            for (int e = 0; e < 4; e++) {
                const int r = m0 + wm * 32 + mi * 16 + (lane >> 2) + (e >> 1) * 8;
                const int c = wn * 32 + nj * 8 + (lane & 3) * 2 + (e & 1);
                g_part[((size_t)split * Bdim + r) * CPAD + c] = acc[mi][nj][e];
            }
}

// ======================= per-row epilogue (label detect inlined) =======================
__global__ __launch_bounds__(128) void epilogue_kernel(const void* __restrict__ labels) {
    const int row = blockIdx.x;
    const int t   = threadIdx.x;

    __shared__ float sv[128];
    __shared__ int   si[128];
    __shared__ float slog[128];
    __shared__ float s_nf;
    __shared__ int   s_ok[2];

    // int64-vs-int32 label layout sniff (values in [0,100) or -1 => int64 high
    // words are all 0/-1; int32 odd words are labels, P(false positive) ~ 0)
    if (t < 64) {
        const int hi = ((const int*)labels)[2 * t + 1];
        const int ok = (hi == 0 || hi == -1) ? 1 : 0;
        unsigned b = __ballot_sync(0xFFFFFFFFu, ok);
        if ((t & 31) == 0) s_ok[t >> 5] = (b == 0xFFFFFFFFu);
    }

    // parallel feature-norm reduction (warp 2)
    if (t >= 64 && t < 96) {
        const int l = t - 64;
        float s = g_nfsq[l * Bdim + row];
#pragma unroll
        for (int off = 16; off > 0; off >>= 1)
            s += __shfl_down_sync(0xFFFFFFFFu, s, off);
        if (l == 0) s_nf = fmaxf(sqrtf(s), 1e-8f);
    }

    float g = 0.f;
#pragma unroll
    for (int s = 0; s < SPLITS; s++)
        g += g_part[((size_t)s * Bdim + row) * CPAD + t];
    __syncthreads();

    const float logit = (t < Cdim) ? 10.0f * g / s_nf : -CUDART_INF_F;
    slog[t] = logit;
    sv[t]   = logit;
    si[t]   = t;
    __syncthreads();

    for (int off = 64; off > 0; off >>= 1) {
        if (t < off) {
            float v2 = sv[t + off]; int i2 = si[t + off];
            if (v2 > sv[t] || (v2 == sv[t] && i2 < si[t])) { sv[t] = v2; si[t] = i2; }
        }
        __syncthreads();
    }
    const float mx   = sv[0];
    const int   amax = si[0];
    __syncthreads();

    sv[t] = (t < Cdim) ? expf(logit - mx) : 0.f;
    __syncthreads();
    for (int off = 64; off > 0; off >>= 1) {
        if (t < off) sv[t] += sv[t + off];
        __syncthreads();
    }

    if (t == 0) {
        const float lse = logf(sv[0]) + mx;
        const int is64 = (s_ok[0] && s_ok[1]) ? 1 : 0;
        long long lab;
        if (is64) lab = ((const long long*)labels)[row];
        else      lab = (long long)((const int*)labels)[row];
        const bool valid = (lab >= 0);
        float nll = 0.f, corr = 0.f;
        if (valid) {
            nll  = lse - slog[(int)lab];
            corr = (amax == (int)lab) ? 1.f : 0.f;
        }
        g_nll[row]  = nll;
        g_corr[row] = corr;
        g_vld[row]  = valid ? 1.f : 0.f;
    }
}

// ======================= finalize =======================
__global__ __launch_bounds__(256) void finalize_kernel(float* __restrict__ out,
                                                       int out_size) {
    __shared__ float sn[256], sc[256], sd[256];
    const int t = threadIdx.x;
    float a = 0.f, b = 0.f, c = 0.f;
    for (int i = t; i < Bdim; i += 256) {
        a += g_nll[i]; b += g_corr[i]; c += g_vld[i];
    }
    sn[t] = a; sc[t] = b; sd[t] = c;
    __syncthreads();
    for (int off = 128; off > 0; off >>= 1) {
        if (t < off) { sn[t] += sn[t + off]; sc[t] += sc[t + off]; sd[t] += sd[t + off]; }
        __syncthreads();
    }
    if (t == 0) {
        const float nv = sd[0];
        out[0] = sn[0] / fmaxf(nv, 1.0f);
        if (out_size > 1) out[1] = sc[0] / (nv + 1e-10f);
    }
}

// ======================= launch =======================
extern "C" void kernel_launch(void* const* d_in, const int* in_sizes, int n_in,
                              void* d_out, int out_size) {
    int fi = 0, li = 0;
    for (int i = 1; i < n_in; i++) {
        if (in_sizes[i] > in_sizes[fi]) fi = i;
        if (in_sizes[i] < in_sizes[li]) li = i;
    }
    int wi = 0;
    for (int i = 0; i < n_in; i++) if (i != fi && i != li) wi = i;

    const float* F = (const float*)d_in[fi];
    const float* W = (const float*)d_in[wi];
    const void*  L = d_in[li];

    cudaFuncSetAttribute(gemm_mma_kernel,
                         cudaFuncAttributeMaxDynamicSharedMemorySize, SMEM_TOTAL);

    prep_w_kernel<<<CPAD, 256>>>(W);
    gemm_mma_kernel<<<dim3(Bdim / BM, SPLITS), 512, SMEM_TOTAL>>>(F);
    epilogue_kernel<<<Bdim, 128>>>(L);
    finalize_kernel<<<1, 256>>>((float*)d_out, out_size);
}

// round 6
// speedup vs baseline: 1.6612x; 1.0171x over previous
#include <cuda_runtime.h>
#include <math_constants.h>
#include <cstdint>

// Problem shape (fixed)
#define Bdim 2048
#define Ddim 25088
#define Cdim 100
#define CPAD 128

#define SPLITS 8
#define KC (Ddim / SPLITS)      // 3136
#define KT 32                   // fp16 K per iteration
#define ITERS (KC / KT)         // 98
#define BM 128

// smem tile geometry: 128 rows x 32 fp16 (64 B), row stride padded to 80 B
#define STR 80
#define TILE_SZ (128 * STR)              // 10240 B
#define BUF_SZ (2 * TILE_SZ)             // A, B
#define SMEM_TOTAL (2 * BUF_SZ)          // 40960 B

#define W32 12544                        // u32 per W row (25088 fp16)

// ---------------- scratch ----------------
__device__ float    g_part[(size_t)SPLITS * Bdim * CPAD];  // 8 MB split partials
__device__ float    g_nfsq[SPLITS * 4 * Bdim];             // feature norm^2 partials
__device__ uint32_t g_wh[(size_t)CPAD * W32];              // normalized W, fp16
__device__ unsigned long long g_loss_fx;                   // fixed-point loss sum (2^-32)
__device__ int      g_corr_acc;
__device__ int      g_vld_acc;

// ---------------- helpers ----------------
__device__ __forceinline__ uint32_t smem_u32(const void* p) {
    uint32_t a;
    asm("{ .reg .u64 t; cvta.to.shared.u64 t, %1; cvt.u32.u64 %0, t; }" : "=r"(a) : "l"(p));
    return a;
}
__device__ __forceinline__ void ldsm4(uint32_t addr, uint32_t& r0, uint32_t& r1,
                                      uint32_t& r2, uint32_t& r3) {
    asm volatile("ldmatrix.sync.aligned.m8n8.x4.shared.b16 {%0,%1,%2,%3}, [%4];"
                 : "=r"(r0), "=r"(r1), "=r"(r2), "=r"(r3) : "r"(addr));
}
__device__ __forceinline__ void mma_f16(float& d0, float& d1, float& d2, float& d3,
                                        uint32_t a0, uint32_t a1, uint32_t a2, uint32_t a3,
                                        uint32_t b0, uint32_t b1) {
    asm volatile("mma.sync.aligned.m16n8k16.row.col.f32.f16.f16.f32 "
                 "{%0,%1,%2,%3}, {%4,%5,%6,%7}, {%8,%9}, {%0,%1,%2,%3};"
                 : "+f"(d0), "+f"(d1), "+f"(d2), "+f"(d3)
                 : "r"(a0), "r"(a1), "r"(a2), "r"(a3), "r"(b0), "r"(b1));
}
__device__ __forceinline__ uint32_t cvt_f16x2(float x, float y) {
    uint32_t r;
    asm("cvt.rn.f16x2.f32 %0, %1, %2;" : "=r"(r) : "f"(y), "f"(x));
    return r;
}
#define CP16(dst, src) asm volatile("cp.async.cg.shared.global [%0], [%1], 16;" :: "r"(dst), "l"(src))
#define CP_COMMIT()    asm volatile("cp.async.commit_group;" ::: "memory")
#define CP_WAIT1()     asm volatile("cp.async.wait_group 1;" ::: "memory")
#define CP_WAIT0()     asm volatile("cp.async.wait_group 0;" ::: "memory")

// ======================= W prep: norm + normalize + fp16 (+acc zeroing) ========
__global__ __launch_bounds__(256) void prep_w_kernel(const float* __restrict__ W) {
    const int row = blockIdx.x;                // 0..127
    const int t   = threadIdx.x;
    __shared__ float red[256];
    __shared__ float s_inv;

    if (row == 0 && t == 0) { g_loss_fx = 0ull; g_corr_acc = 0; g_vld_acc = 0; }

    uint32_t* dh = &g_wh[(size_t)row * W32];
    if (row < Cdim) {
        const float4* r4 = (const float4*)(W + (size_t)row * Ddim);
        float s = 0.f;
        for (int i = t; i < Ddim / 4; i += 256) {
            float4 v = r4[i];
            s += v.x * v.x + v.y * v.y + v.z * v.z + v.w * v.w;
        }
        red[t] = s;
        __syncthreads();
        for (int off = 128; off > 0; off >>= 1) {
            if (t < off) red[t] += red[t + off];
            __syncthreads();
        }
        if (t == 0) s_inv = 1.0f / fmaxf(sqrtf(red[0]), 1e-8f);
        __syncthreads();
        const float inv = s_inv;
        const float2* r2 = (const float2*)(W + (size_t)row * Ddim);
        for (int i = t; i < W32; i += 256) {
            float2 v = r2[i];
            dh[i] = cvt_f16x2(v.x * inv, v.y * inv);
        }
    } else {
        for (int i = t; i < W32; i += 256) dh[i] = 0u;
    }
}

// ======================= HMMA fp16 GEMM (N trimmed to 104) =======================
// grid (Bdim/BM, SPLITS), 512 threads. Warps: wm = w&3 (M), wn = w>>2 (N).
// wn==3 computes only n8 group 0 (cols 96-103) -> balanced across SMSPs.
__global__ void __launch_bounds__(512, 1)
gemm_mma_kernel(const float* __restrict__ F) {
    extern __shared__ char smem[];
    const uint32_t sbase = smem_u32(smem);

    const int t     = threadIdx.x;
    const int lane  = t & 31;
    const int w     = t >> 5;
    const int m0    = blockIdx.x * BM;
    const int split = blockIdx.y;
    const int k0    = split * KC;

    // ---- loader mapping ----
    const int row = t >> 2;
    const int q   = t & 3;

    const float4* gA = (const float4*)(F + (size_t)(m0 + row) * Ddim + k0) + 2 * q;
    const uint32_t stsA_off = row * STR + q * 16;
    const char* srcB = (const char*)g_wh + (size_t)row * (W32 * 4) + (size_t)k0 * 2 + q * 16;
    const uint32_t dstB_off = TILE_SZ + row * STR + q * 16;

    // ---- MMA mapping: wm on SMSP-varying bits, wn across SMSP groups ----
    const int wm = w & 3;
    const int wn = w >> 2;
    const int nmax = (wn == 3) ? 1 : 4;         // n8 groups this warp computes
    const uint32_t aAddr0 = sbase + (wm * 32 + (lane & 15)) * STR + (lane >> 4) * 16;
    const uint32_t bAddr0 = sbase + TILE_SZ +
        (wn * 32 + (lane & 7) + (lane >> 4) * 8) * STR + ((lane >> 3) & 1) * 16;

    float acc[2][4][4];
#pragma unroll
    for (int i = 0; i < 2; i++)
#pragma unroll
        for (int j = 0; j < 4; j++)
#pragma unroll
            for (int e = 0; e < 4; e++) acc[i][j][e] = 0.f;

    float nf = 0.f;
    float4 ra[2][2];

    // prologue: A tiles 0,1 into regs; B tile 0 cp.async into buf0
    ra[0][0] = gA[0];  ra[0][1] = gA[1];
    ra[1][0] = gA[8];  ra[1][1] = gA[9];
    CP16(sbase + dstB_off, srcB);
    CP_COMMIT();

    for (int it = 0; it < ITERS; it++) {
        const uint32_t bufo = (it & 1) ? BUF_SZ : 0;
        const uint32_t nbuf = (it & 1) ? 0 : BUF_SZ;
        const int slot = it & 1;

        __syncthreads();

        if (it + 1 < ITERS) {
            CP16(sbase + nbuf + dstB_off, srcB + (size_t)(it + 1) * 64);
            CP_COMMIT();
        }

        // convert + store A tile `it`
        {
            float4 v0 = ra[slot][0], v1 = ra[slot][1];
            nf += v0.x * v0.x + v0.y * v0.y + v0.z * v0.z + v0.w * v0.w
                + v1.x * v1.x + v1.y * v1.y + v1.z * v1.z + v1.w * v1.w;
            uint4 pk;
            pk.x = cvt_f16x2(v0.x, v0.y);
            pk.y = cvt_f16x2(v0.z, v0.w);
            pk.z = cvt_f16x2(v1.x, v1.y);
            pk.w = cvt_f16x2(v1.z, v1.w);
            *(uint4*)(smem + bufo + stsA_off) = pk;
        }

        if (it + 2 < ITERS) {
            ra[slot][0] = gA[(it + 2) * 8];
            ra[slot][1] = gA[(it + 2) * 8 + 1];
        }

        if (it + 1 < ITERS) { CP_WAIT1(); } else { CP_WAIT0(); }
        __syncthreads();

#pragma unroll
        for (int ks = 0; ks < 2; ks++) {
            uint32_t ah[2][4], bh[2][4];
#pragma unroll
            for (int mi = 0; mi < 2; mi++) {
                const uint32_t a = aAddr0 + bufo + mi * 16 * STR + ks * 32;
                ldsm4(a, ah[mi][0], ah[mi][1], ah[mi][2], ah[mi][3]);
            }
            {   // B n16 group 0 always; group 1 only for full warps
                const uint32_t b = bAddr0 + bufo + ks * 32;
                ldsm4(b, bh[0][0], bh[0][1], bh[0][2], bh[0][3]);
                if (nmax == 4)
                    ldsm4(b + 16 * STR, bh[1][0], bh[1][1], bh[1][2], bh[1][3]);
            }
#pragma unroll
            for (int mi = 0; mi < 2; mi++)
#pragma unroll
                for (int nj = 0; nj < 4; nj++) {
                    if (nj >= nmax) break;
                    float* d = acc[mi][nj];
                    mma_f16(d[0], d[1], d[2], d[3],
                            ah[mi][0], ah[mi][1], ah[mi][2], ah[mi][3],
                            bh[nj >> 1][2 * (nj & 1)], bh[nj >> 1][2 * (nj & 1) + 1]);
                }
        }
    }

    // feature norm^2 partial
    g_nfsq[(split * 4 + q) * Bdim + (m0 + row)] = nf;

    // write live partials only (cols >= 104 never read meaningfully)
#pragma unroll
    for (int mi = 0; mi < 2; mi++)
#pragma unroll
        for (int nj = 0; nj < 4; nj++) {
            if (nj >= nmax) break;
#pragma unroll
            for (int e = 0; e < 4; e++) {
                const int r = m0 + wm * 32 + mi * 16 + (lane >> 2) + (e >> 1) * 8;
                const int c = wn * 32 + nj * 8 + (lane & 3) * 2 + (e & 1);
                g_part[((size_t)split * Bdim + r) * CPAD + c] = acc[mi][nj][e];
            }
        }
}

// ======================= per-row epilogue (atomic accumulate) =======================
__global__ __launch_bounds__(128) void epilogue_kernel(const void* __restrict__ labels) {
    const int row = blockIdx.x;
    const int t   = threadIdx.x;

    __shared__ float sv[128];
    __shared__ int   si[128];
    __shared__ float slog[128];
    __shared__ float s_nf;
    __shared__ int   s_ok[2];

    // int64-vs-int32 label layout sniff
    if (t < 64) {
        const int hi = ((const int*)labels)[2 * t + 1];
        const int ok = (hi == 0 || hi == -1) ? 1 : 0;
        unsigned b = __ballot_sync(0xFFFFFFFFu, ok);
        if ((t & 31) == 0) s_ok[t >> 5] = (b == 0xFFFFFFFFu);
    }

    // feature-norm reduction (warp 2)
    if (t >= 64 && t < 96) {
        const int l = t - 64;
        float s = g_nfsq[l * Bdim + row];
#pragma unroll
        for (int off = 16; off > 0; off >>= 1)
            s += __shfl_down_sync(0xFFFFFFFFu, s, off);
        if (l == 0) s_nf = fmaxf(sqrtf(s), 1e-8f);
    }

    float g = 0.f;
    if (t < Cdim) {
#pragma unroll
        for (int s = 0; s < SPLITS; s++)
            g += g_part[((size_t)s * Bdim + row) * CPAD + t];
    }
    __syncthreads();

    const float logit = (t < Cdim) ? 10.0f * g / s_nf : -CUDART_INF_F;
    slog[t] = logit;
    sv[t]   = logit;
    si[t]   = t;
    __syncthreads();

    for (int off = 64; off > 0; off >>= 1) {
        if (t < off) {
            float v2 = sv[t + off]; int i2 = si[t + off];
            if (v2 > sv[t] || (v2 == sv[t] && i2 < si[t])) { sv[t] = v2; si[t] = i2; }
        }
        __syncthreads();
    }
    const float mx   = sv[0];
    const int   amax = si[0];
    __syncthreads();

    sv[t] = (t < Cdim) ? expf(logit - mx) : 0.f;
    __syncthreads();
    for (int off = 64; off > 0; off >>= 1) {
        if (t < off) sv[t] += sv[t + off];
        __syncthreads();
    }

    if (t == 0) {
        const float lse = logf(sv[0]) + mx;
        const int is64 = (s_ok[0] && s_ok[1]) ? 1 : 0;
        long long lab;
        if (is64) lab = ((const long long*)labels)[row];
        else      lab = (long long)((const int*)labels)[row];
        if (lab >= 0) {
            const float nll = lse - slog[(int)lab];
            // fixed-point (2^-32) integer accumulate: order-independent -> deterministic
            const unsigned long long fx =
                (unsigned long long)(fmax((double)nll, 0.0) * 4294967296.0 + 0.5);
            atomicAdd(&g_loss_fx, fx);
            if (amax == (int)lab) atomicAdd(&g_corr_acc, 1);
            atomicAdd(&g_vld_acc, 1);
        }
    }
}

// ======================= finalize (scalar) =======================
__global__ void finalize_kernel(float* __restrict__ out, int out_size) {
    if (threadIdx.x == 0) {
        const double loss_sum = (double)g_loss_fx * (1.0 / 4294967296.0);
        const float nv = (float)g_vld_acc;
        out[0] = (float)(loss_sum / (double)fmaxf(nv, 1.0f));
        if (out_size > 1) out[1] = (float)g_corr_acc / (nv + 1e-10f);
    }
}

// ======================= launch =======================
extern "C" void kernel_launch(void* const* d_in, const int* in_sizes, int n_in,
                              void* d_out, int out_size) {
    int fi = 0, li = 0;
    for (int i = 1; i < n_in; i++) {
        if (in_sizes[i] > in_sizes[fi]) fi = i;
        if (in_sizes[i] < in_sizes[li]) li = i;
    }
    int wi = 0;
    for (int i = 0; i < n_in; i++) if (i != fi && i != li) wi = i;

    const float* F = (const float*)d_in[fi];
    const float* W = (const float*)d_in[wi];
    const void*  L = d_in[li];

    cudaFuncSetAttribute(gemm_mma_kernel,
                         cudaFuncAttributeMaxDynamicSharedMemorySize, SMEM_TOTAL);

    prep_w_kernel<<<CPAD, 256>>>(W);
    gemm_mma_kernel<<<dim3(Bdim / BM, SPLITS), 512, SMEM_TOTAL>>>(F);
    epilogue_kernel<<<Bdim, 128>>>(L);
    finalize_kernel<<<1, 32>>>((float*)d_out, out_size);
}

// round 7
// speedup vs baseline: 1.7890x; 1.0770x over previous
#include <cuda_runtime.h>
#include <math_constants.h>
#include <cstdint>

// Problem shape (fixed)
#define Bdim 2048
#define Ddim 25088
#define Cdim 100
#define CPAD 128

#define SPLITS 8
#define KC (Ddim / SPLITS)      // 3136
#define KT 64                   // fp16 K per iteration
#define ITERS (KC / KT)         // 49
#define BM 128

// smem tile geometry: 128 rows x 64 fp16 (128 B), row stride padded to 144 B
#define STR 144
#define TILE_SZ (128 * STR)              // 18432 B
#define BUF_SZ (2 * TILE_SZ)             // A, B
#define SMEM_TOTAL (2 * BUF_SZ)          // 73728 B

#define W32 12544                        // u32 per W row (25088 fp16)

// ---------------- scratch ----------------
__device__ float    g_part[(size_t)SPLITS * Bdim * CPAD];  // 8 MB split partials
__device__ float    g_nfsq[SPLITS * 4 * Bdim];             // feature norm^2 partials
__device__ uint32_t g_wh[(size_t)CPAD * W32];              // normalized W, fp16
__device__ unsigned long long g_loss_fx;                   // fixed-point loss sum (2^-32)
__device__ int      g_corr_acc;
__device__ int      g_vld_acc;
__device__ unsigned g_ticket;

// ---------------- helpers ----------------
__device__ __forceinline__ uint32_t smem_u32(const void* p) {
    uint32_t a;
    asm("{ .reg .u64 t; cvta.to.shared.u64 t, %1; cvt.u32.u64 %0, t; }" : "=r"(a) : "l"(p));
    return a;
}
__device__ __forceinline__ void ldsm4(uint32_t addr, uint32_t& r0, uint32_t& r1,
                                      uint32_t& r2, uint32_t& r3) {
    asm volatile("ldmatrix.sync.aligned.m8n8.x4.shared.b16 {%0,%1,%2,%3}, [%4];"
                 : "=r"(r0), "=r"(r1), "=r"(r2), "=r"(r3) : "r"(addr));
}
__device__ __forceinline__ void mma_f16(float& d0, float& d1, float& d2, float& d3,
                                        uint32_t a0, uint32_t a1, uint32_t a2, uint32_t a3,
                                        uint32_t b0, uint32_t b1) {
    asm volatile("mma.sync.aligned.m16n8k16.row.col.f32.f16.f16.f32 "
                 "{%0,%1,%2,%3}, {%4,%5,%6,%7}, {%8,%9}, {%0,%1,%2,%3};"
                 : "+f"(d0), "+f"(d1), "+f"(d2), "+f"(d3)
                 : "r"(a0), "r"(a1), "r"(a2), "r"(a3), "r"(b0), "r"(b1));
}
__device__ __forceinline__ uint32_t cvt_f16x2(float x, float y) {
    uint32_t r;
    asm("cvt.rn.f16x2.f32 %0, %1, %2;" : "=r"(r) : "f"(y), "f"(x));
    return r;
}
#define CP16(dst, src) asm volatile("cp.async.cg.shared.global [%0], [%1], 16;" :: "r"(dst), "l"(src))
#define CP_COMMIT()    asm volatile("cp.async.commit_group;" ::: "memory")
#define CP_WAIT1()     asm volatile("cp.async.wait_group 1;" ::: "memory")
#define CP_WAIT0()     asm volatile("cp.async.wait_group 0;" ::: "memory")

// ======================= W prep: norm + normalize + fp16 (+acc zeroing) ========
__global__ __launch_bounds__(256) void prep_w_kernel(const float* __restrict__ W) {
    const int row = blockIdx.x;                // 0..127
    const int t   = threadIdx.x;
    __shared__ float red[256];
    __shared__ float s_inv;

    if (row == 0 && t == 0) {
        g_loss_fx = 0ull; g_corr_acc = 0; g_vld_acc = 0; g_ticket = 0u;
    }

    uint32_t* dh = &g_wh[(size_t)row * W32];
    if (row < Cdim) {
        const float4* r4 = (const float4*)(W + (size_t)row * Ddim);
        float s = 0.f;
        for (int i = t; i < Ddim / 4; i += 256) {
            float4 v = r4[i];
            s += v.x * v.x + v.y * v.y + v.z * v.z + v.w * v.w;
        }
        red[t] = s;
        __syncthreads();
        for (int off = 128; off > 0; off >>= 1) {
            if (t < off) red[t] += red[t + off];
            __syncthreads();
        }
        if (t == 0) s_inv = 1.0f / fmaxf(sqrtf(red[0]), 1e-8f);
        __syncthreads();
        const float inv = s_inv;
        const float2* r2 = (const float2*)(W + (size_t)row * Ddim);
        for (int i = t; i < W32; i += 256) {
            float2 v = r2[i];
            dh[i] = cvt_f16x2(v.x * inv, v.y * inv);
        }
    } else {
        for (int i = t; i < W32; i += 256) dh[i] = 0u;
    }
}

// ======================= HMMA fp16 GEMM (KT=64, N trimmed to 104) ==============
// grid (Bdim/BM, SPLITS), 512 threads. Warps: wm = w&3 (SMSP), wn = w>>2.
__global__ void __launch_bounds__(512, 1)
gemm_mma_kernel(const float* __restrict__ F) {
    extern __shared__ char smem[];
    const uint32_t sbase = smem_u32(smem);

    const int t     = threadIdx.x;
    const int lane  = t & 31;
    const int w     = t >> 5;
    const int m0    = blockIdx.x * BM;
    const int split = blockIdx.y;
    const int k0    = split * KC;

    // ---- loader mapping: row = t/4, q = t&3 covers 16 floats (32 B fp16) ----
    const int row = t >> 2;
    const int q   = t & 3;

    const float4* gA = (const float4*)(F + (size_t)(m0 + row) * Ddim + k0) + q * 4;
    const uint32_t stsA_off = row * STR + q * 32;
    const char* srcB = (const char*)g_wh + (size_t)row * (W32 * 4) + (size_t)k0 * 2 + q * 32;
    const uint32_t dstB_off = TILE_SZ + row * STR + q * 32;

    // ---- MMA mapping ----
    const int wm = w & 3;
    const int wn = w >> 2;
    const int nmax = (wn == 3) ? 1 : 4;
    const uint32_t aAddr0 = sbase + (wm * 32 + (lane & 15)) * STR + (lane >> 4) * 16;
    const uint32_t bAddr0 = sbase + TILE_SZ +
        (wn * 32 + (lane & 7) + (lane >> 4) * 8) * STR + ((lane >> 3) & 1) * 16;

    float acc[2][4][4];
#pragma unroll
    for (int i = 0; i < 2; i++)
#pragma unroll
        for (int j = 0; j < 4; j++)
#pragma unroll
            for (int e = 0; e < 4; e++) acc[i][j][e] = 0.f;

    float nf = 0.f;
    float4 ra[4];

    // prologue: A tile 0 into regs; B tile 0 cp.async into buf0
#pragma unroll
    for (int j = 0; j < 4; j++) ra[j] = gA[j];
    CP16(sbase + dstB_off, srcB);
    CP16(sbase + dstB_off + 16, srcB + 16);
    CP_COMMIT();

    for (int it = 0; it < ITERS; it++) {
        const uint32_t bufo = (it & 1) ? BUF_SZ : 0;
        const uint32_t nbuf = (it & 1) ? 0 : BUF_SZ;

        __syncthreads();   // buf writable (prior MMA reads done)

        // issue B(it+1) into other buffer
        if (it + 1 < ITERS) {
            const char* s = srcB + (size_t)(it + 1) * 128;
            CP16(sbase + nbuf + dstB_off, s);
            CP16(sbase + nbuf + dstB_off + 16, s + 16);
            CP_COMMIT();
        }

        // convert + store A tile `it` (16 floats -> 8 f16x2 -> 2 STS.128)
        {
            uint32_t pk[8];
#pragma unroll
            for (int j = 0; j < 4; j++) {
                float4 v = ra[j];
                nf += v.x * v.x + v.y * v.y + v.z * v.z + v.w * v.w;
                pk[2 * j]     = cvt_f16x2(v.x, v.y);
                pk[2 * j + 1] = cvt_f16x2(v.z, v.w);
            }
            *(uint4*)(smem + bufo + stsA_off)      = make_uint4(pk[0], pk[1], pk[2], pk[3]);
            *(uint4*)(smem + bufo + stsA_off + 16) = make_uint4(pk[4], pk[5], pk[6], pk[7]);
        }

        // single-stage A prefetch (covered by the long MMA phase)
        if (it + 1 < ITERS) {
#pragma unroll
            for (int j = 0; j < 4; j++) ra[j] = gA[(it + 1) * 16 + j];
        }

        if (it + 1 < ITERS) { CP_WAIT1(); } else { CP_WAIT0(); }
        __syncthreads();   // tile `it` fully visible

        // MMA: 4 k16 steps
#pragma unroll
        for (int ks = 0; ks < 4; ks++) {
            uint32_t ah[2][4], bh[2][4];
#pragma unroll
            for (int mi = 0; mi < 2; mi++) {
                const uint32_t a = aAddr0 + bufo + mi * 16 * STR + ks * 32;
                ldsm4(a, ah[mi][0], ah[mi][1], ah[mi][2], ah[mi][3]);
            }
            {
                const uint32_t b = bAddr0 + bufo + ks * 32;
                ldsm4(b, bh[0][0], bh[0][1], bh[0][2], bh[0][3]);
                if (nmax == 4)
                    ldsm4(b + 16 * STR, bh[1][0], bh[1][1], bh[1][2], bh[1][3]);
            }
#pragma unroll
            for (int mi = 0; mi < 2; mi++)
#pragma unroll
                for (int nj = 0; nj < 4; nj++) {
                    if (nj >= nmax) break;
                    float* d = acc[mi][nj];
                    mma_f16(d[0], d[1], d[2], d[3],
                            ah[mi][0], ah[mi][1], ah[mi][2], ah[mi][3],
                            bh[nj >> 1][2 * (nj & 1)], bh[nj >> 1][2 * (nj & 1) + 1]);
                }
        }
    }

    // feature norm^2 partial
    g_nfsq[(split * 4 + q) * Bdim + (m0 + row)] = nf;

    // write live partials
#pragma unroll
    for (int mi = 0; mi < 2; mi++)
#pragma unroll
        for (int nj = 0; nj < 4; nj++) {
            if (nj >= nmax) break;
#pragma unroll
            for (int e = 0; e < 4; e++) {
                const int r = m0 + wm * 32 + mi * 16 + (lane >> 2) + (e >> 1) * 8;
                const int c = wn * 32 + nj * 8 + (lane & 3) * 2 + (e & 1);
                g_part[((size_t)split * Bdim + r) * CPAD + c] = acc[mi][nj][e];
            }
        }
}

// ======================= per-row epilogue + fused finalize =======================
__global__ __launch_bounds__(128) void epilogue_kernel(const void* __restrict__ labels,
                                                       float* __restrict__ out,
                                                       int out_size) {
    const int row = blockIdx.x;
    const int t   = threadIdx.x;

    __shared__ float sv[128];
    __shared__ int   si[128];
    __shared__ float slog[128];
    __shared__ float s_nf;
    __shared__ int   s_ok[2];
    __shared__ unsigned s_tick;

    // int64-vs-int32 label layout sniff
    if (t < 64) {
        const int hi = ((const int*)labels)[2 * t + 1];
        const int ok = (hi == 0 || hi == -1) ? 1 : 0;
        unsigned b = __ballot_sync(0xFFFFFFFFu, ok);
        if ((t & 31) == 0) s_ok[t >> 5] = (b == 0xFFFFFFFFu);
    }

    // feature-norm reduction (warp 2)
    if (t >= 64 && t < 96) {
        const int l = t - 64;
        float s = g_nfsq[l * Bdim + row];
#pragma unroll
        for (int off = 16; off > 0; off >>= 1)
            s += __shfl_down_sync(0xFFFFFFFFu, s, off);
        if (l == 0) s_nf = fmaxf(sqrtf(s), 1e-8f);
    }

    float g = 0.f;
    if (t < Cdim) {
#pragma unroll
        for (int s = 0; s < SPLITS; s++)
            g += g_part[((size_t)s * Bdim + row) * CPAD + t];
    }
    __syncthreads();

    const float logit = (t < Cdim) ? 10.0f * g / s_nf : -CUDART_INF_F;
    slog[t] = logit;
    sv[t]   = logit;
    si[t]   = t;
    __syncthreads();

    for (int off = 64; off > 0; off >>= 1) {
        if (t < off) {
            float v2 = sv[t + off]; int i2 = si[t + off];
            if (v2 > sv[t] || (v2 == sv[t] && i2 < si[t])) { sv[t] = v2; si[t] = i2; }
        }
        __syncthreads();
    }
    const float mx   = sv[0];
    const int   amax = si[0];
    __syncthreads();

    sv[t] = (t < Cdim) ? expf(logit - mx) : 0.f;
    __syncthreads();
    for (int off = 64; off > 0; off >>= 1) {
        if (t < off) sv[t] += sv[t + off];
        __syncthreads();
    }

    if (t == 0) {
        const float lse = logf(sv[0]) + mx;
        const int is64 = (s_ok[0] && s_ok[1]) ? 1 : 0;
        long long lab;
        if (is64) lab = ((const long long*)labels)[row];
        else      lab = (long long)((const int*)labels)[row];
        if (lab >= 0) {
            const float nll = lse - slog[(int)lab];
            // fixed-point (2^-32) integer accumulate: order-independent, deterministic
            const unsigned long long fx =
                (unsigned long long)(fmax((double)nll, 0.0) * 4294967296.0 + 0.5);
            atomicAdd(&g_loss_fx, fx);
            if (amax == (int)lab) atomicAdd(&g_corr_acc, 1);
            atomicAdd(&g_vld_acc, 1);
        }
        __threadfence();
        s_tick = atomicAdd(&g_ticket, 1u);
    }
    __syncthreads();

    // last block finalizes
    if (s_tick == (unsigned)(gridDim.x - 1) && t == 0) {
        const double loss_sum = (double)g_loss_fx * (1.0 / 4294967296.0);
        const float nv = (float)g_vld_acc;
        out[0] = (float)(loss_sum / (double)fmaxf(nv, 1.0f));
        if (out_size > 1) out[1] = (float)g_corr_acc / (nv + 1e-10f);
    }
}

// ======================= launch =======================
extern "C" void kernel_launch(void* const* d_in, const int* in_sizes, int n_in,
                              void* d_out, int out_size) {
    int fi = 0, li = 0;
    for (int i = 1; i < n_in; i++) {
        if (in_sizes[i] > in_sizes[fi]) fi = i;
        if (in_sizes[i] < in_sizes[li]) li = i;
    }
    int wi = 0;
    for (int i = 0; i < n_in; i++) if (i != fi && i != li) wi = i;

    const float* F = (const float*)d_in[fi];
    const float* W = (const float*)d_in[wi];
    const void*  L = d_in[li];

    cudaFuncSetAttribute(gemm_mma_kernel,
                         cudaFuncAttributeMaxDynamicSharedMemorySize, SMEM_TOTAL);

    prep_w_kernel<<<CPAD, 256>>>(W);
    gemm_mma_kernel<<<dim3(Bdim / BM, SPLITS), 512, SMEM_TOTAL>>>(F);
    epilogue_kernel<<<Bdim, 128>>>(L, (float*)d_out, out_size);
}